// round 4
// baseline (speedup 1.0000x reference)
#include <cuda_runtime.h>
#include <math.h>

#define NC     124
#define CPAD   128
#define CH     64
#define IN_HW  120
#define OUT_HW 480
#define NPIX   (OUT_HW * OUT_HW)   // 230400
#define NTAP   (IN_HW * IN_HW)     // 14400
#define EPSV   1e-8f

typedef unsigned long long ull;

// ---------------- f32x2 packed helpers (sm_103a FFMA2) ----------------
__device__ __forceinline__ ull pk2(float lo, float hi) {
    ull r; asm("mov.b64 %0, {%1,%2};" : "=l"(r) : "f"(lo), "f"(hi)); return r;
}
__device__ __forceinline__ void upk2(ull v, float& lo, float& hi) {
    asm("mov.b64 {%0,%1}, %2;" : "=f"(lo), "=f"(hi) : "l"(v));
}
__device__ __forceinline__ void ffma2(ull& d, ull a, ull b) {
    asm("fma.rn.f32x2 %0, %1, %2, %3;" : "=l"(d) : "l"(a), "l"(b), "l"(d));
}
__device__ __forceinline__ ull fadd2(ull a, ull b) {
    ull r; asm("add.rn.f32x2 %0, %1, %2;" : "=l"(r) : "l"(a), "l"(b)); return r;
}

// ---------------- static device scratch ----------------
__device__ __align__(16) float g_featsT[NTAP * CH];   // (tap, ch)
__device__ int   g_iszero[NC];
__device__ __align__(16) float g_gram[NTAP * 8];      // S,H,V,D,AD per tap
__device__ __align__(16) float g_G[NTAP * CPAD];      // f_t . mn_c
__device__ __align__(16) float g_C[NTAP * CPAD];      // selected coefficient
__device__ float g_acc[NC * CH];
__device__ float g_den[CPAD];                          // sum s (or count if iszero)
__device__ float g_cnt[CPAD];                          // pixel count per class

// ---------------- K1: transpose feats + zero accumulators ----------------
__global__ __launch_bounds__(256) void k_init(const float* __restrict__ feats) {
    __shared__ float tile[32][33];
    const int bid = blockIdx.x;                 // 0..899
    const int tid = threadIdx.x;
    const int tx = tid & 31, ty = tid >> 5;
    const int spT = (bid % 450) * 32;
    const int chT = (bid / 450) * 32;

#pragma unroll
    for (int k = 0; k < 32; k += 8)
        tile[ty + k][tx] = feats[(chT + ty + k) * NTAP + spT + tx];
    __syncthreads();
#pragma unroll
    for (int k = 0; k < 32; k += 8)
        g_featsT[(spT + ty + k) * CH + chT + tx] = tile[tx][ty + k];

    const int gid = bid * 256 + tid;            // 230400 threads
    float4 z = make_float4(0.f, 0.f, 0.f, 0.f);
    ((float4*)g_C)[gid * 2]     = z;            // 230400*8 = NTAP*CPAD
    ((float4*)g_C)[gid * 2 + 1] = z;
    if (gid < NC * CH) g_acc[gid] = 0.f;
    if (gid < CPAD) { g_den[gid] = 0.f; g_cnt[gid] = 0.f; }
}

// ---------------- K2: neighbor Gram arrays (warp per tap) ----------------
__global__ __launch_bounds__(1024) void k_gram() {
    const int t = blockIdx.x * 32 + (threadIdx.x >> 5);
    const int lane = threadIdx.x & 31;
    const int y = t / IN_HW, x = t - y * IN_HW;
    const int xp = min(x + 1, IN_HW - 1), yp = min(y + 1, IN_HW - 1);
    const float2 a = *(const float2*)&g_featsT[(y  * IN_HW + x ) * CH + lane * 2];
    const float2 b = *(const float2*)&g_featsT[(y  * IN_HW + xp) * CH + lane * 2];
    const float2 c = *(const float2*)&g_featsT[(yp * IN_HW + x ) * CH + lane * 2];
    const float2 d = *(const float2*)&g_featsT[(yp * IN_HW + xp) * CH + lane * 2];
    float s  = a.x * a.x + a.y * a.y;
    float h  = a.x * b.x + a.y * b.y;
    float vv = a.x * c.x + a.y * c.y;
    float dd = a.x * d.x + a.y * d.y;
    float ad = b.x * c.x + b.y * c.y;
#pragma unroll
    for (int m = 16; m; m >>= 1) {
        s  += __shfl_xor_sync(0xffffffffu, s,  m);
        h  += __shfl_xor_sync(0xffffffffu, h,  m);
        vv += __shfl_xor_sync(0xffffffffu, vv, m);
        dd += __shfl_xor_sync(0xffffffffu, dd, m);
        ad += __shfl_xor_sync(0xffffffffu, ad, m);
    }
    if (lane == 0) {
        float* o = &g_gram[t * 8];
        o[0] = s; o[1] = h; o[2] = vv; o[3] = dd; o[4] = ad;
    }
}

// ---------------- K3: G table (fused memory-normalize, f32x2 GEMM) ----------------
__global__ __launch_bounds__(128) void k_G(const float* __restrict__ memory) {
    __shared__ __align__(16) ull fsm[8 * 32];   // 8 taps * 64 ch packed
    const int c = threadIdx.x;
    const bool valid = c < NC;

    // load + normalize memory row in-registers (redundant per block, trivial)
    ull m2[32];
    float n2 = 0.f; int isz = 1;
#pragma unroll
    for (int k = 0; k < 16; k++) {
        float4 v = valid ? ((const float4*)memory)[c * 16 + k]
                         : make_float4(0.f, 0.f, 0.f, 0.f);
        n2 += v.x * v.x + v.y * v.y + v.z * v.z + v.w * v.w;
        isz &= (v.x == 0.f) & (v.y == 0.f) & (v.z == 0.f) & (v.w == 0.f);
        m2[2 * k]     = pk2(v.x, v.y);
        m2[2 * k + 1] = pk2(v.z, v.w);
    }
    const float inv = 1.0f / fmaxf(sqrtf(n2), EPSV);
    const ull inv2 = pk2(inv, inv);
#pragma unroll
    for (int k = 0; k < 32; k++) { ull t = 0; ffma2(t, m2[k], inv2); m2[k] = t; }
    if (blockIdx.x == 0 && valid) g_iszero[c] = isz;

    const int base = blockIdx.x * 24;           // 600 blocks * 24 taps
    for (int g = 0; g < 3; g++) {
        const int t0 = base + g * 8;
        __syncthreads();
        ((float4*)fsm)[c] = *(const float4*)&g_featsT[t0 * CH + c * 4];
        __syncthreads();
#pragma unroll
        for (int tt = 0; tt < 8; tt++) {
            const ulonglong2* fr = (const ulonglong2*)&fsm[tt * 32];
            ull a0 = 0, a1 = 0, a2 = 0, a3 = 0;
#pragma unroll
            for (int k = 0; k < 16; k++) {
                ulonglong2 q = fr[k];
                if (k & 1) { ffma2(a2, q.x, m2[2 * k]); ffma2(a3, q.y, m2[2 * k + 1]); }
                else       { ffma2(a0, q.x, m2[2 * k]); ffma2(a1, q.y, m2[2 * k + 1]); }
            }
            a0 = fadd2(a0, a2); a1 = fadd2(a1, a3); a0 = fadd2(a0, a1);
            float lo, hi; upk2(a0, lo, hi);
            if (valid) g_G[(t0 + tt) * CPAD + c] = lo + hi;
        }
    }
}

// ---------------- K4: per-pixel weight + coefficient scatter ----------------
__global__ __launch_bounds__(512) void k_phaseA(const int* __restrict__ seg) {
    __shared__ float s_den[CPAD], s_cnt[CPAD];
    __shared__ int   s_isz[CPAD];
    const int t = threadIdx.x;
    if (t < CPAD) {
        s_den[t] = 0.f; s_cnt[t] = 0.f;
        s_isz[t] = (t < NC) ? g_iszero[t] : 0;
    }
    __syncthreads();

    const int i = blockIdx.x * 512 + t;         // exact NPIX coverage
    const int oy = i / OUT_HW, ox = i - oy * OUT_HW;
    const int c = seg[i];
    const float fy = 0.25f * (float)oy - 0.375f;
    const float fx = 0.25f * (float)ox - 0.375f;
    const int by = (int)floorf(fy), bx = (int)floorf(fx);
    int y0, x0; float u, v;
    if (by < 0)               { y0 = 0;         u = 0.f; }
    else if (by >= IN_HW - 1) { y0 = IN_HW - 1; u = 0.f; }
    else                      { y0 = by;        u = fy - (float)by; }
    if (bx < 0)               { x0 = 0;         v = 0.f; }
    else if (bx >= IN_HW - 1) { x0 = IN_HW - 1; v = 0.f; }
    else                      { x0 = bx;        v = fx - (float)bx; }
    const int yp = min(y0 + 1, IN_HW - 1), xp = min(x0 + 1, IN_HW - 1);
    const float wu0 = 1.f - u, wv0 = 1.f - v;
    const float w00 = wu0 * wv0, w01 = wu0 * v, w10 = u * wv0, w11 = u * v;
    const int t00 = y0 * IN_HW + x0, t01 = y0 * IN_HW + xp;
    const int t10 = yp * IN_HW + x0, t11 = yp * IN_HW + xp;

    const float dot = w00 * g_G[t00 * CPAD + c] + w01 * g_G[t01 * CPAD + c]
                    + w10 * g_G[t10 * CPAD + c] + w11 * g_G[t11 * CPAD + c];

    const float4 q00 = *(const float4*)&g_gram[t00 * 8];   // S,H,V,D
    const float ad00 = g_gram[t00 * 8 + 4];
    const float4 q01 = *(const float4*)&g_gram[t01 * 8];
    const float4 q10 = *(const float4*)&g_gram[t10 * 8];
    const float S11  = g_gram[t11 * 8];

    float n2 = w00 * w00 * q00.x + w01 * w01 * q01.x + w10 * w10 * q10.x + w11 * w11 * S11
             + 2.f * (w00 * w01 * q00.y + w10 * w11 * q10.y
                    + w00 * w10 * q00.z + w01 * w11 * q01.z
                    + w00 * w11 * q00.w + w01 * w10 * ad00);
    n2 = fmaxf(n2, 0.f);
    const float s = 1.f - dot / fmaxf(sqrtf(n2), EPSV);

    const int   isz = s_isz[c];
    const float cm  = isz ? 1.0f : s;           // selected coefficient multiplier
    atomicAdd(&g_C[t00 * CPAD + c], cm * w00);
    atomicAdd(&g_C[t01 * CPAD + c], cm * w01);
    atomicAdd(&g_C[t10 * CPAD + c], cm * w10);
    atomicAdd(&g_C[t11 * CPAD + c], cm * w11);
    atomicAdd(&s_den[c], cm);
    atomicAdd(&s_cnt[c], 1.0f);

    __syncthreads();
    if (t < NC) {
        atomicAdd(&g_den[t], s_den[t]);
        atomicAdd(&g_cnt[t], s_cnt[t]);
    }
}

// ---------------- K5: output GEMM  acc[c][ch] = sum_t C[t][c] f[t][ch] ----------------
__global__ __launch_bounds__(128) void k_out() {
    __shared__ __align__(16) ull fsm[8 * 32];
    const int c = threadIdx.x;
    const bool valid = c < NC;
    ull acc2[32];
#pragma unroll
    for (int k = 0; k < 32; k++) acc2[k] = 0;

    const int base = blockIdx.x * 48;           // 300 blocks * 48 taps
    for (int g = 0; g < 6; g++) {
        const int t0 = base + g * 8;
        float cv[8];
#pragma unroll
        for (int tt = 0; tt < 8; tt++)
            cv[tt] = g_C[(t0 + tt) * CPAD + c];  // cols 124..127 are zero
        __syncthreads();
        ((float4*)fsm)[c] = *(const float4*)&g_featsT[t0 * CH + c * 4];
        __syncthreads();
#pragma unroll
        for (int tt = 0; tt < 8; tt++) {
            const ull c2 = pk2(cv[tt], cv[tt]);
            const ulonglong2* fr = (const ulonglong2*)&fsm[tt * 32];
#pragma unroll
            for (int k = 0; k < 16; k++) {
                ulonglong2 q = fr[k];
                ffma2(acc2[2 * k],     c2, q.x);
                ffma2(acc2[2 * k + 1], c2, q.y);
            }
        }
    }
    if (valid) {
#pragma unroll
        for (int k = 0; k < 32; k++) {
            float lo, hi; upk2(acc2[k], lo, hi);
            atomicAdd(&g_acc[c * CH + 2 * k],     lo);
            atomicAdd(&g_acc[c * CH + 2 * k + 1], hi);
        }
    }
}

// ---------------- K6: final blend ----------------
__global__ __launch_bounds__(64) void k_blend(const float* __restrict__ memory,
                                              float* __restrict__ out) {
    const int c = blockIdx.x, ch = threadIdx.x;
    const float mem = memory[c * CH + ch];
    const float cnt = g_cnt[c];
    float o;
    if (cnt < 0.5f) {
        o = mem;                                            // class absent
    } else if (g_iszero[c]) {
        o = g_acc[c * CH + ch] / fmaxf(g_den[c], 1.0f);     // class mean (den==cnt)
    } else {
        const float dv = g_den[c];
        const float denom = (dv != 0.0f) ? dv : 1.0f;
        o = 0.9f * mem + 0.1f * (g_acc[c * CH + ch] / denom);
    }
    out[c * CH + ch] = o;
}

// ---------------- launch ----------------
extern "C" void kernel_launch(void* const* d_in, const int* in_sizes, int n_in,
                              void* d_out, int out_size) {
    const float* feats  = (const float*)d_in[0];   // (1,64,120,120)
    const float* memory = (const float*)d_in[1];   // (124,1,64)
    const int*   seg    = (const int*)d_in[2];     // (1,480,480)
    float* out = (float*)d_out;                    // (124,1,64)

    k_init<<<900, 256>>>(feats);
    k_gram<<<450, 1024>>>();
    k_G<<<600, 128>>>(memory);
    k_phaseA<<<450, 512>>>(seg);
    k_out<<<300, 128>>>();
    k_blend<<<NC, 64>>>(memory, out);
}